// round 13
// baseline (speedup 1.0000x reference)
#include <cuda_runtime.h>
#include <cuda_bf16.h>
#include <cstdint>

// ---------------- problem constants ----------------
#define BB    8192
#define TT    406
#define DD    10
#define PP    64
#define KD    (TT*DD)            // 4060
#define MTILE 128
#define NMT   (BB/MTILE)         // 64
#define KSPL  2
#define TC8   8                  // t per chunk
#define NCHT  51                 // ceil(406/8)
#define CSPL0 26                 // chunks in split 0
#define SLOTU 6                  // u32 cols per t: 5 data pairs + (m|csq, 0)
#define KCN16 6                  // k16-steps per chunk (96 bf16 / 16)
#define TSU   56                 // tile stride in u32; half-warp LDS.64 conflict-free
#define MARGIN 6.0f

// smem (u32/floats): msk[2][1024] + 2 x (A[128*56] + B[64*56]) u32
#define MSK_F   1024
#define A_U     (MTILE*TSU)      // 7168
#define B_U     (PP*TSU)         // 3584
#define BUF_U   (A_U + B_U)      // 10752
#define SMEM_WORDS (2*MSK_F + 2*BUF_U)   // 23552
#define SMEM_MAIN  (SMEM_WORDS*4)        // 94208 B

// ---------------- scratch (device globals, no alloc) ----------------
__device__ float g_partial[KSPL][BB][PP]; // (-2*cross + sq_p) partials
__device__ float g_sqx[KSPL][BB];         // sum m*x^2 partials
__device__ int   g_idx[BB];               // argmin index per b

// pack two floats -> bf16x2 (lo, hi)
__device__ __forceinline__ uint32_t bf2(float lo, float hi) {
    uint32_t r;
    asm("cvt.rn.bf16x2.f32 %0, %1, %2;" : "=r"(r) : "f"(hi), "f"(lo));
    return r;
}
// pair-interleave on u32 columns: group of 8, position 2j+h holds col j+4h
// -> LDS.64 at (kc*8 + tig*2) yields u32 cols (tig, tig+4) = bf16 k {2t,2t+1},{2t+8,2t+9}
__device__ __forceinline__ int kmap32(int c) {
    return (c >> 3) * 8 + ((c & 3) << 1) + ((c >> 2) & 1);
}

// ---------------- kernel 1: bf16 m16n8k16 mma.sync GEMM ----------------
__global__ void __launch_bounds__(512, 1) main_kernel(
    const float* __restrict__ x, const float* __restrict__ mask,
    const float* __restrict__ proto,
    float* __restrict__ out_xcopy, float* __restrict__ out_mask)
{
    extern __shared__ uint32_t sm[];
    float*    msk_s = (float*)sm;           // [2][1024]
    uint32_t* buf_s = sm + 2 * MSK_F;       // [2][A_U + B_U]

    const int tid = threadIdx.x;
    const int wid = tid >> 5, lane = tid & 31;
    const int mt  = blockIdx.x >> 1;
    const int ks  = blockIdx.x & 1;
    const int b0  = mt * MTILE;
    const int c_beg = ks ? CSPL0 : 0;
    const int c_end = ks ? NCHT  : CSPL0;

    // mma roles: 16 warps = 4m x 4n, warp tile 32x16
    const int tig = lane & 3, grp = lane >> 2;
    const int wm = wid & 3, wn = wid >> 2;
    const int boff = wm * 32, noff = wn * 16;

    float acc[2][2][4];
    #pragma unroll
    for (int i = 0; i < 2; i++)
        #pragma unroll
        for (int j = 0; j < 2; j++)
            #pragma unroll
            for (int q = 0; q < 4; q++) acc[i][j][q] = 0.f;
    float sqr[5] = {0.f, 0.f, 0.f, 0.f, 0.f};

    // staging registers
    float4 xv[5];
    float4 bv[3];
    float2 mnext;
    float  csqv;

    const int pb = tid & 63, tqb = tid >> 6;   // B csq role
    const int mrow = tid >> 2, mseg = tid & 3; // mask role

    auto ldg_x = [&](int c) {
        #pragma unroll
        for (int r = 0; r < 5; r++) {
            int idx = tid + 512 * r;
            int row = idx / 20, q = idx - row * 20;
            int goff = c * 80 + 4 * q;
            xv[r] = (goff < KD) ? __ldcs((const float4*)(x + (size_t)(b0 + row) * KD + goff))
                                : make_float4(0.f, 0.f, 0.f, 0.f);
        }
    };
    auto ldg_B = [&](int c) {
        #pragma unroll
        for (int r = 0; r < 3; r++) {
            int idx = tid + 512 * r;
            float4 v = make_float4(0.f, 0.f, 0.f, 0.f);
            if (idx < 1280) {
                int p = idx / 20, q = idx - p * 20;
                int goff = c * 80 + 4 * q;
                if (goff < KD) v = *(const float4*)(proto + (size_t)p * KD + goff);
            }
            bv[r] = v;
        }
        int tg = c * TC8 + tqb;
        csqv = 0.f;
        if (tg < TT) {
            const float2* cp = (const float2*)(proto + ((size_t)pb * TT + tg) * DD);
            #pragma unroll
            for (int q = 0; q < 5; q++) {
                float2 z = cp[q];
                csqv = fmaf(z.x, z.x, csqv);
                csqv = fmaf(z.y, z.y, csqv);
            }
        }
    };
    auto ldg_msk = [&](int c) {
        int t = c * TC8 + mseg * 2;
        float m0 = (t     < TT) ? __ldcs(mask + (size_t)(b0 + mrow) * TT + t)     : 0.f;
        float m1 = (t + 1 < TT) ? __ldcs(mask + (size_t)(b0 + mrow) * TT + t + 1) : 0.f;
        mnext = make_float2(m0, m1);
    };
    auto sts_msk = [&](int c) {
        float* ms = msk_s + (c & 1) * MSK_F;
        ms[mrow * 8 + mseg * 2]     = mnext.x;
        ms[mrow * 8 + mseg * 2 + 1] = mnext.y;
        int t = c * TC8 + mseg * 2;
        if (t     < TT) __stcs(out_mask + (size_t)(b0 + mrow) * TT + t,     mnext.x);
        if (t + 1 < TT) __stcs(out_mask + (size_t)(b0 + mrow) * TT + t + 1, mnext.y);
    };
    auto sts_AB = [&](int c) {
        uint32_t* a_s = buf_s + (c & 1) * BUF_U;
        uint32_t* b_s = a_s + A_U;
        const float* ms = msk_s + (c & 1) * MSK_F;
        // A: coalesced xcopy + masked bf16-pair scatter + fp32 sqx
        #pragma unroll
        for (int r = 0; r < 5; r++) {
            int idx = tid + 512 * r;
            int row = idx / 20, q = idx - row * 20;
            int goff = c * 80 + 4 * q;
            if (goff < KD)
                __stcs((float4*)(out_xcopy + (size_t)(b0 + row) * KD + goff), xv[r]);
            float e[4] = {xv[r].x, xv[r].y, xv[r].z, xv[r].w};
            #pragma unroll
            for (int u = 0; u < 4; u += 2) {   // two bf16 pairs per float4
                int off = 4 * q + u;           // even
                int t = off / 10, s = off - 10 * t;   // s even, <=8
                float m = ms[row * 8 + t];
                float v0 = m * e[u], v1 = m * e[u + 1];
                sqr[r] = fmaf(v0, e[u], sqr[r]);
                sqr[r] = fmaf(v1, e[u + 1], sqr[r]);
                a_s[row * TSU + kmap32(t * SLOTU + (s >> 1))] = bf2(v0, v1);
            }
        }
        // A mask cols (pair = (m, 0)): 2 per thread
        #pragma unroll
        for (int j = 0; j < 2; j++) {
            int u2 = tid + 512 * j;
            int row = u2 >> 3, t = u2 & 7;
            a_s[row * TSU + kmap32(t * SLOTU + 5)] = bf2(ms[row * 8 + t], 0.f);
        }
        // B: -2c bf16-pair scatter
        #pragma unroll
        for (int r = 0; r < 3; r++) {
            int idx = tid + 512 * r;
            if (idx < 1280) {
                int p = idx / 20, q = idx - p * 20;
                float e[4] = {bv[r].x, bv[r].y, bv[r].z, bv[r].w};
                #pragma unroll
                for (int u = 0; u < 4; u += 2) {
                    int off = 4 * q + u;
                    int t = off / 10, s = off - 10 * t;
                    b_s[p * TSU + kmap32(t * SLOTU + (s >> 1))] = bf2(-2.f * e[u], -2.f * e[u + 1]);
                }
            }
        }
        // B csq col (pair = (csq, 0)): 1 per thread
        b_s[pb * TSU + kmap32(tqb * SLOTU + 5)] = bf2(csqv, 0.f);
    };
    auto mma_chunk = [&](int c) {
        const uint32_t* a_s = buf_s + (c & 1) * BUF_U;
        const uint32_t* b_s = a_s + A_U;
        #pragma unroll
        for (int kc = 0; kc < KCN16; kc++) {
            uint32_t af[2][4], bf[2][2];
            #pragma unroll
            for (int i = 0; i < 2; i++) {
                int rb = boff + i * 16 + grp;
                uint2 pa0 = *(const uint2*)(a_s + rb * TSU + kc * 8 + tig * 2);
                uint2 pa1 = *(const uint2*)(a_s + (rb + 8) * TSU + kc * 8 + tig * 2);
                af[i][0] = pa0.x; af[i][2] = pa0.y;   // (a0, a2) row rb
                af[i][1] = pa1.x; af[i][3] = pa1.y;   // (a1, a3) row rb+8
            }
            #pragma unroll
            for (int j = 0; j < 2; j++) {
                int cp2 = noff + j * 8 + grp;
                uint2 pbv = *(const uint2*)(b_s + cp2 * TSU + kc * 8 + tig * 2);
                bf[j][0] = pbv.x; bf[j][1] = pbv.y;   // (b0, b1)
            }
            #pragma unroll
            for (int i = 0; i < 2; i++)
                #pragma unroll
                for (int j = 0; j < 2; j++)
                    asm volatile(
                        "mma.sync.aligned.m16n8k16.row.col.f32.bf16.bf16.f32 "
                        "{%0,%1,%2,%3}, {%4,%5,%6,%7}, {%8,%9}, {%0,%1,%2,%3};"
                        : "+f"(acc[i][j][0]), "+f"(acc[i][j][1]),
                          "+f"(acc[i][j][2]), "+f"(acc[i][j][3])
                        : "r"(af[i][0]), "r"(af[i][1]), "r"(af[i][2]), "r"(af[i][3]),
                          "r"(bf[j][0]), "r"(bf[j][1]));
        }
    };

    // prologue
    ldg_msk(c_beg); sts_msk(c_beg);
    if (c_beg + 1 < c_end) ldg_msk(c_beg + 1);
    ldg_x(c_beg); ldg_B(c_beg);
    __syncthreads();

    // 1-barrier pipeline: sts(c) | sts_msk(c+1) | sync | ldg(c+1) | mma(c)
    for (int c = c_beg; c < c_end; ++c) {
        sts_AB(c);
        if (c + 1 < c_end) sts_msk(c + 1);
        __syncthreads();
        if (c + 1 < c_end) { ldg_x(c + 1); ldg_B(c + 1); }
        if (c + 2 < c_end) ldg_msk(c + 2);
        mma_chunk(c);
    }

    // ---- sqx reduction (argmin invariant to per-b offset; order-free) ----
    __syncthreads();
    {
        float* red = msk_s;   // reuse
        if (tid < MTILE) red[tid] = 0.f;
        __syncthreads();
        #pragma unroll
        for (int r = 0; r < 5; r++) {
            int row = (tid + 512 * r) / 20;
            atomicAdd(&red[row], sqr[r]);
        }
        __syncthreads();
        if (tid < MTILE) g_sqx[ks][b0 + tid] = red[tid];
    }

    // ---- epilogue: accumulators -> g_partial ----
    #pragma unroll
    for (int i = 0; i < 2; i++) {
        int rb = b0 + boff + i * 16 + grp;
        #pragma unroll
        for (int j = 0; j < 2; j++) {
            int cc = noff + j * 8 + 2 * tig;
            *(float2*)&g_partial[ks][rb][cc]     = make_float2(acc[i][j][0], acc[i][j][1]);
            *(float2*)&g_partial[ks][rb + 8][cc] = make_float2(acc[i][j][2], acc[i][j][3]);
        }
    }
}

// ---------------- kernel 2: argmin (warp per b) -> dist, idx, label, g_idx ----------------
__global__ void __launch_bounds__(256) argmin_kernel(
    const float* __restrict__ x, const float* __restrict__ mask,
    const float* __restrict__ proto, const int* __restrict__ label,
    float* __restrict__ out_dist, float* __restrict__ out_idx,
    float* __restrict__ out_label)
{
    const int tid = threadIdx.x, w = tid >> 5, lane = tid & 31;
    const int b = blockIdx.x * 8 + w;

    float sx = g_sqx[0][b] + g_sqx[1][b];
    float d0 = sx + g_partial[0][b][lane]      + g_partial[1][b][lane];
    float d1 = sx + g_partial[0][b][lane + 32] + g_partial[1][b][lane + 32];
    out_dist[(size_t)b * PP + lane]      = d0;
    out_dist[(size_t)b * PP + lane + 32] = d1;

    float bd; int bpick;
    if (d1 < d0) { bd = d1; bpick = lane + 32; } else { bd = d0; bpick = lane; }
    #pragma unroll
    for (int o = 16; o > 0; o >>= 1) {
        float od = __shfl_xor_sync(0xffffffffu, bd, o);
        int   op = __shfl_xor_sync(0xffffffffu, bpick, o);
        if (od < bd || (od == bd && op < bpick)) { bd = od; bpick = op; }
    }
    unsigned c0 = __ballot_sync(0xffffffffu, d0 < bd + MARGIN);
    unsigned c1 = __ballot_sync(0xffffffffu, d1 < bd + MARGIN);
    unsigned long long cm = ((unsigned long long)c1 << 32) | (unsigned long long)c0;
    int idx = bpick;
    if (__popcll(cm) > 1) {   // exact fp32 rescore of near-ties
        float best = 3.4e38f; int bi = PP;
        while (cm) {
            int p = __ffsll((long long)cm) - 1;
            cm &= cm - 1;
            float r = 0.f;
            const float* xrow = x + (size_t)b * KD;
            const float* crow = proto + (size_t)p * KD;
            for (int t = lane; t < TT; t += 32) {
                float m = mask[(size_t)b * TT + t];
                if (m != 0.f) {
                    const float* xp = xrow + t * DD;
                    const float* cp = crow + t * DD;
                    float dot = 0.f, cps = 0.f;
                    #pragma unroll
                    for (int d = 0; d < DD; d++) {
                        float cv = cp[d];
                        dot = fmaf(xp[d], cv, dot);
                        cps = fmaf(cv, cv, cps);
                    }
                    r += cps - 2.f * dot;
                }
            }
            #pragma unroll
            for (int o = 16; o > 0; o >>= 1) r += __shfl_xor_sync(0xffffffffu, r, o);
            if (r < best) { best = r; bi = p; }   // ascending p: first-occurrence
        }
        idx = bi;
    }
    if (lane == 0) {
        g_idx[b]     = idx;
        out_idx[b]   = (float)idx;
        out_label[b] = (float)label[b];
    }
}

// ---------------- kernel 3: gather out_seq[b] = proto[g_idx[b]] ----------------
__global__ void __launch_bounds__(256) gather_kernel(
    const float* __restrict__ proto, float* __restrict__ out_seq)
{
    const int b = blockIdx.x;
    const int idx = g_idx[b];
    const float4* src = (const float4*)(proto + (size_t)idx * KD);
    float4* dst = (float4*)(out_seq + (size_t)b * KD);
    const int tid = threadIdx.x;
    #pragma unroll
    for (int r = 0; r < 3; r++) {
        int i = tid + 256 * r;
        __stcs(dst + i, __ldg(src + i));
    }
    int i3 = tid + 768;
    if (i3 < KD / 4) __stcs(dst + i3, __ldg(src + i3));
}

// ---------------- launch ----------------
extern "C" void kernel_launch(void* const* d_in, const int* in_sizes, int n_in,
                              void* d_out, int out_size) {
    const float* x     = (const float*)d_in[0];
    const int*   label = (const int*)d_in[1];
    const float* mask  = (const float*)d_in[2];
    const float* proto = (const float*)d_in[3];
    float* out = (float*)d_out;

    const size_t o_seq   = 0;
    const size_t o_xcopy = (size_t)BB * KD;
    const size_t o_dist  = o_xcopy * 2;
    const size_t o_idx   = o_dist + (size_t)BB * PP;
    const size_t o_label = o_idx + BB;
    const size_t o_mask  = o_label + BB;

    cudaFuncSetAttribute(main_kernel, cudaFuncAttributeMaxDynamicSharedMemorySize, SMEM_MAIN);

    main_kernel<<<NMT * KSPL, 512, SMEM_MAIN>>>(x, mask, proto,
                                                out + o_xcopy, out + o_mask);
    argmin_kernel<<<BB / 8, 256>>>(x, mask, proto, label,
                                   out + o_dist, out + o_idx, out + o_label);
    gather_kernel<<<BB, 256>>>(proto, out + o_seq);
}

// round 14
// speedup vs baseline: 1.3498x; 1.3498x over previous
#include <cuda_runtime.h>
#include <cuda_bf16.h>
#include <cstdint>

// ---------------- problem constants ----------------
#define BB    8192
#define TT    406
#define DD    10
#define PP    64
#define KD    (TT*DD)            // 4060
#define MTILE 128
#define NMT   (BB/MTILE)         // 64
#define KSPL  2
#define TC8   8                  // t per chunk
#define NCHT  51                 // ceil(406/8)
#define CSPL0 26                 // chunks in split 0
#define SLOT  11                 // k-slots per t: 10 dims + (m | csq)
#define KCN   11                 // k8-chunks per chunk (88/8)
#define TS    104                // tile stride; LDS.64 phases conflict-free (104 mod 32 = 8)
#define MARGIN 2.0f

// smem (floats): msk[2][1024], then 2 x (A[128*104] + B[64*104])
#define MSK_F   1024
#define A_F     (MTILE*TS)       // 13312
#define B_F     (PP*TS)          // 6656
#define BUF_F   (A_F + B_F)      // 19968
#define SMEM_FLOATS (2*MSK_F + 2*BUF_F)
#define SMEM_MAIN   (SMEM_FLOATS*4)    // 167936 B

// ---------------- scratch (device globals, no alloc) ----------------
__device__ float g_partial[KSPL][BB][PP]; // (-2*cross + sq_p) partials
__device__ float g_sqx[KSPL][BB];         // sum m*x^2 partials

__device__ __forceinline__ uint32_t tf32r(float v) {
    uint32_t r; asm("cvt.rna.tf32.f32 %0, %1;" : "=r"(r) : "f"(v)); return r;
}
// pair-interleave map: k in [0,88) -> tile column; LDS.64 at kc*8+tig*2 yields (k0+tig, k0+tig+4)
__device__ __forceinline__ int kmap(int k) {
    return (k >> 3) * 8 + ((k & 3) << 1) + ((k >> 2) & 1);
}

// ---------------- kernel 1: TF32 mma.sync GEMM (131us champion, verbatim) ----------------
__global__ void __launch_bounds__(512, 1) main_kernel(
    const float* __restrict__ x, const float* __restrict__ mask,
    const float* __restrict__ proto,
    float* __restrict__ out_xcopy, float* __restrict__ out_mask)
{
    extern __shared__ float sm[];
    float* msk_s = sm;                 // [2][1024]
    float* buf_s = sm + 2 * MSK_F;     // [2][A_F + B_F]

    const int tid = threadIdx.x;
    const int wid = tid >> 5, lane = tid & 31;
    const int mt  = blockIdx.x >> 1;
    const int ks  = blockIdx.x & 1;
    const int b0  = mt * MTILE;
    const int c_beg = ks ? CSPL0 : 0;
    const int c_end = ks ? NCHT  : CSPL0;

    // mma roles: 16 warps = 4m x 4n
    const int tig = lane & 3, grp = lane >> 2;
    const int wm = wid & 3, wn = wid >> 2;
    const int boff = wm * 32, noff = wn * 16;

    float acc[2][2][4];
    #pragma unroll
    for (int i = 0; i < 2; i++)
        #pragma unroll
        for (int j = 0; j < 2; j++)
            #pragma unroll
            for (int q = 0; q < 4; q++) acc[i][j][q] = 0.f;
    float sqr[5] = {0.f, 0.f, 0.f, 0.f, 0.f};

    // staging registers
    float4 xv[5];
    float4 bv[3];
    float2 mnext;
    float  csqv;

    const int pb = tid & 63, tqb = tid >> 6;   // B csq role
    const int mrow = tid >> 2, mseg = tid & 3; // mask role

    auto ldg_x = [&](int c) {
        #pragma unroll
        for (int r = 0; r < 5; r++) {
            int idx = tid + 512 * r;
            int row = idx / 20, q = idx - row * 20;
            int goff = c * 80 + 4 * q;
            xv[r] = (goff < KD) ? __ldcs((const float4*)(x + (size_t)(b0 + row) * KD + goff))
                                : make_float4(0.f, 0.f, 0.f, 0.f);
        }
    };
    auto ldg_B = [&](int c) {
        #pragma unroll
        for (int r = 0; r < 3; r++) {
            int idx = tid + 512 * r;
            float4 v = make_float4(0.f, 0.f, 0.f, 0.f);
            if (idx < 1280) {
                int p = idx / 20, q = idx - p * 20;
                int goff = c * 80 + 4 * q;
                if (goff < KD) v = *(const float4*)(proto + (size_t)p * KD + goff);
            }
            bv[r] = v;
        }
        int tg = c * TC8 + tqb;
        csqv = 0.f;
        if (tg < TT) {
            const float2* cp = (const float2*)(proto + ((size_t)pb * TT + tg) * DD);
            #pragma unroll
            for (int q = 0; q < 5; q++) {
                float2 z = cp[q];
                csqv = fmaf(z.x, z.x, csqv);
                csqv = fmaf(z.y, z.y, csqv);
            }
        }
    };
    auto ldg_msk = [&](int c) {
        int t = c * TC8 + mseg * 2;
        float m0 = (t     < TT) ? __ldcs(mask + (size_t)(b0 + mrow) * TT + t)     : 0.f;
        float m1 = (t + 1 < TT) ? __ldcs(mask + (size_t)(b0 + mrow) * TT + t + 1) : 0.f;
        mnext = make_float2(m0, m1);
    };
    auto sts_msk = [&](int c) {
        float* ms = msk_s + (c & 1) * MSK_F;
        ms[mrow * 8 + mseg * 2]     = mnext.x;
        ms[mrow * 8 + mseg * 2 + 1] = mnext.y;
        int t = c * TC8 + mseg * 2;
        if (t     < TT) __stcs(out_mask + (size_t)(b0 + mrow) * TT + t,     mnext.x);
        if (t + 1 < TT) __stcs(out_mask + (size_t)(b0 + mrow) * TT + t + 1, mnext.y);
    };
    auto sts_AB = [&](int c) {
        float* a_s = buf_s + (c & 1) * BUF_F;
        float* b_s = a_s + A_F;
        const float* ms = msk_s + (c & 1) * MSK_F;
        // A: coalesced xcopy + masked tf32 scatter + fp32 sqx
        #pragma unroll
        for (int r = 0; r < 5; r++) {
            int idx = tid + 512 * r;
            int row = idx / 20, q = idx - row * 20;
            int goff = c * 80 + 4 * q;
            if (goff < KD)
                __stcs((float4*)(out_xcopy + (size_t)(b0 + row) * KD + goff), xv[r]);
            float e[4] = {xv[r].x, xv[r].y, xv[r].z, xv[r].w};
            #pragma unroll
            for (int u = 0; u < 4; u++) {
                int off = 4 * q + u;
                int t = off / 10, s = off - 10 * t;
                float m = ms[row * 8 + t];
                float vf = m * e[u];
                sqr[r] = fmaf(vf, e[u], sqr[r]);
                a_s[row * TS + kmap(t * SLOT + s)] = __uint_as_float(tf32r(vf));
            }
        }
        // A mask slots: 2 per thread (0/1 exact in tf32)
        #pragma unroll
        for (int j = 0; j < 2; j++) {
            int u2 = tid + 512 * j;
            int row = u2 >> 3, t = u2 & 7;
            a_s[row * TS + kmap(t * SLOT + 10)] = ms[row * 8 + t];
        }
        // B: -2c tf32 scatter
        #pragma unroll
        for (int r = 0; r < 3; r++) {
            int idx = tid + 512 * r;
            if (idx < 1280) {
                int p = idx / 20, q = idx - p * 20;
                float e[4] = {bv[r].x, bv[r].y, bv[r].z, bv[r].w};
                #pragma unroll
                for (int u = 0; u < 4; u++) {
                    int off = 4 * q + u;
                    int t = off / 10, s = off - 10 * t;
                    b_s[p * TS + kmap(t * SLOT + s)] = __uint_as_float(tf32r(-2.f * e[u]));
                }
            }
        }
        // B csq slot: 1 per thread
        b_s[pb * TS + kmap(tqb * SLOT + 10)] = __uint_as_float(tf32r(csqv));
    };
    auto mma_chunk = [&](int c) {
        const float* a_s = buf_s + (c & 1) * BUF_F;
        const float* b_s = a_s + A_F;
        #pragma unroll
        for (int kc = 0; kc < KCN; kc++) {
            uint32_t af[2][4], bf[2][2];
            #pragma unroll
            for (int i = 0; i < 2; i++) {
                int rb = boff + i * 16 + grp;
                float2 pa0 = *(const float2*)(a_s + rb * TS + kc * 8 + tig * 2);
                float2 pa1 = *(const float2*)(a_s + (rb + 8) * TS + kc * 8 + tig * 2);
                af[i][0] = __float_as_uint(pa0.x); af[i][2] = __float_as_uint(pa0.y);
                af[i][1] = __float_as_uint(pa1.x); af[i][3] = __float_as_uint(pa1.y);
            }
            #pragma unroll
            for (int j = 0; j < 2; j++) {
                int cp2 = noff + j * 8 + grp;
                float2 pbv = *(const float2*)(b_s + cp2 * TS + kc * 8 + tig * 2);
                bf[j][0] = __float_as_uint(pbv.x); bf[j][1] = __float_as_uint(pbv.y);
            }
            #pragma unroll
            for (int i = 0; i < 2; i++)
                #pragma unroll
                for (int j = 0; j < 2; j++)
                    asm volatile(
                        "mma.sync.aligned.m16n8k8.row.col.f32.tf32.tf32.f32 "
                        "{%0,%1,%2,%3}, {%4,%5,%6,%7}, {%8,%9}, {%0,%1,%2,%3};"
                        : "+f"(acc[i][j][0]), "+f"(acc[i][j][1]),
                          "+f"(acc[i][j][2]), "+f"(acc[i][j][3])
                        : "r"(af[i][0]), "r"(af[i][1]), "r"(af[i][2]), "r"(af[i][3]),
                          "r"(bf[j][0]), "r"(bf[j][1]));
        }
    };

    // prologue
    ldg_msk(c_beg); sts_msk(c_beg);
    if (c_beg + 1 < c_end) ldg_msk(c_beg + 1);
    ldg_x(c_beg); ldg_B(c_beg);
    __syncthreads();

    // 1-barrier pipeline: sts(c) | sts_msk(c+1) | sync | ldg(c+1) | mma(c)
    for (int c = c_beg; c < c_end; ++c) {
        sts_AB(c);
        if (c + 1 < c_end) sts_msk(c + 1);
        __syncthreads();
        if (c + 1 < c_end) { ldg_x(c + 1); ldg_B(c + 1); }
        if (c + 2 < c_end) ldg_msk(c + 2);
        mma_chunk(c);
    }

    // ---- sqx reduction (argmin invariant to per-b offset; order-free) ----
    __syncthreads();
    {
        float* red = msk_s;   // reuse
        if (tid < MTILE) red[tid] = 0.f;
        __syncthreads();
        #pragma unroll
        for (int r = 0; r < 5; r++) {
            int row = (tid + 512 * r) / 20;
            atomicAdd(&red[row], sqr[r]);
        }
        __syncthreads();
        if (tid < MTILE) g_sqx[ks][b0 + tid] = red[tid];
    }

    // ---- epilogue: accumulators -> g_partial ----
    #pragma unroll
    for (int i = 0; i < 2; i++) {
        int rb = b0 + boff + i * 16 + grp;
        #pragma unroll
        for (int j = 0; j < 2; j++) {
            int cc = noff + j * 8 + 2 * tig;
            *(float2*)&g_partial[ks][rb][cc]     = make_float2(acc[i][j][0], acc[i][j][1]);
            *(float2*)&g_partial[ks][rb + 8][cc] = make_float2(acc[i][j][2], acc[i][j][3]);
        }
    }
}

// ---------------- kernel 2: fused finalize — warp per b, no block syncs ----------------
__global__ void __launch_bounds__(256) finalize_kernel(
    const float* __restrict__ x, const float* __restrict__ mask,
    const float* __restrict__ proto, const int* __restrict__ label,
    float* __restrict__ out_seq, float* __restrict__ out_dist,
    float* __restrict__ out_idx, float* __restrict__ out_label)
{
    const int tid = threadIdx.x, w = tid >> 5, lane = tid & 31;
    const int b = blockIdx.x * 8 + w;

    float sx = g_sqx[0][b] + g_sqx[1][b];
    float d0 = sx + g_partial[0][b][lane]      + g_partial[1][b][lane];
    float d1 = sx + g_partial[0][b][lane + 32] + g_partial[1][b][lane + 32];
    out_dist[(size_t)b * PP + lane]      = d0;
    out_dist[(size_t)b * PP + lane + 32] = d1;

    float bd; int bpick;
    if (d1 < d0) { bd = d1; bpick = lane + 32; } else { bd = d0; bpick = lane; }
    #pragma unroll
    for (int o = 16; o > 0; o >>= 1) {
        float od = __shfl_xor_sync(0xffffffffu, bd, o);
        int   op = __shfl_xor_sync(0xffffffffu, bpick, o);
        if (od < bd || (od == bd && op < bpick)) { bd = od; bpick = op; }
    }
    unsigned c0 = __ballot_sync(0xffffffffu, d0 < bd + MARGIN);
    unsigned c1 = __ballot_sync(0xffffffffu, d1 < bd + MARGIN);
    unsigned long long cm = ((unsigned long long)c1 << 32) | (unsigned long long)c0;
    int idx = bpick;
    if (__popcll(cm) > 1) {   // rare: exact fp32 rescore of near-ties
        float best = 3.4e38f; int bi = PP;
        while (cm) {
            int p = __ffsll((long long)cm) - 1;
            cm &= cm - 1;
            float r = 0.f;
            const float* xrow = x + (size_t)b * KD;
            const float* crow = proto + (size_t)p * KD;
            for (int t = lane; t < TT; t += 32) {
                float m = mask[(size_t)b * TT + t];
                if (m != 0.f) {
                    const float* xp = xrow + t * DD;
                    const float* cp = crow + t * DD;
                    float dot = 0.f, cps = 0.f;
                    #pragma unroll
                    for (int d = 0; d < DD; d++) {
                        float cv = cp[d];
                        dot = fmaf(xp[d], cv, dot);
                        cps = fmaf(cv, cv, cps);
                    }
                    r += cps - 2.f * dot;
                }
            }
            #pragma unroll
            for (int o = 16; o > 0; o >>= 1) r += __shfl_xor_sync(0xffffffffu, r, o);
            if (r < best) { best = r; bi = p; }   // ascending p: first-occurrence
        }
        idx = bi;
    }
    if (lane == 0) {
        out_idx[b]   = (float)idx;
        out_label[b] = (float)label[b];
    }

    // same warp gathers its row: out_seq[b] = proto[idx] (L2-hot source)
    const float4* src = (const float4*)(proto + (size_t)idx * KD);
    float4* dst = (float4*)(out_seq + (size_t)b * KD);
    int i = lane;
    #pragma unroll 4
    for (; i + 96 < KD / 4; i += 128) {
        float4 v0 = __ldg(src + i), v1 = __ldg(src + i + 32);
        float4 v2 = __ldg(src + i + 64), v3 = __ldg(src + i + 96);
        __stcs(dst + i,      v0); __stcs(dst + i + 32, v1);
        __stcs(dst + i + 64, v2); __stcs(dst + i + 96, v3);
    }
    for (; i < KD / 4; i += 32) __stcs(dst + i, __ldg(src + i));
}

// ---------------- launch ----------------
extern "C" void kernel_launch(void* const* d_in, const int* in_sizes, int n_in,
                              void* d_out, int out_size) {
    const float* x     = (const float*)d_in[0];
    const int*   label = (const int*)d_in[1];
    const float* mask  = (const float*)d_in[2];
    const float* proto = (const float*)d_in[3];
    float* out = (float*)d_out;

    const size_t o_seq   = 0;
    const size_t o_xcopy = (size_t)BB * KD;
    const size_t o_dist  = o_xcopy * 2;
    const size_t o_idx   = o_dist + (size_t)BB * PP;
    const size_t o_label = o_idx + BB;
    const size_t o_mask  = o_label + BB;

    cudaFuncSetAttribute(main_kernel, cudaFuncAttributeMaxDynamicSharedMemorySize, SMEM_MAIN);

    main_kernel<<<NMT * KSPL, 512, SMEM_MAIN>>>(x, mask, proto,
                                                out + o_xcopy, out + o_mask);
    finalize_kernel<<<BB / 8, 256>>>(x, mask, proto, label,
                                     out + o_seq, out + o_dist,
                                     out + o_idx, out + o_label);
}

// round 15
// speedup vs baseline: 1.3705x; 1.0153x over previous
#include <cuda_runtime.h>
#include <cuda_bf16.h>
#include <cstdint>

// ---------------- problem constants ----------------
#define BB    8192
#define TT    406
#define DD    10
#define PP    64
#define KD    (TT*DD)            // 4060
#define MTILE 128
#define NMT   (BB/MTILE)         // 64
#define KSPL  2
#define TC8   8                  // t per chunk
#define NCHT  51                 // ceil(406/8)
#define CSPL0 26                 // chunks in split 0
#define SLOT  11                 // k-slots per t: 10 dims + (m | csq)
#define KCN   11                 // k8-chunks per chunk (88/8)
#define TS    104                // tile stride; LDS.64 phases conflict-free (104 mod 32 = 8)
#define MARGIN 1.0f

// smem (floats): msk[2][1024], then 2 x (A[128*104] + B[64*104])
#define MSK_F   1024
#define A_F     (MTILE*TS)       // 13312
#define B_F     (PP*TS)          // 6656
#define BUF_F   (A_F + B_F)      // 19968
#define SMEM_FLOATS (2*MSK_F + 2*BUF_F)
#define SMEM_MAIN   (SMEM_FLOATS*4)    // 167936 B

// ---------------- scratch (device globals, no alloc) ----------------
__device__ float g_partial[KSPL][BB][PP]; // (-2*cross + sq_p) partials
__device__ float g_sqx[KSPL][BB];         // sum m*x^2 partials

__device__ __forceinline__ uint32_t tf32r(float v) {
    uint32_t r; asm("cvt.rna.tf32.f32 %0, %1;" : "=r"(r) : "f"(v)); return r;
}
// pair-interleave map: k in [0,88) -> tile column; LDS.64 at kc*8+tig*2 yields (k0+tig, k0+tig+4)
__device__ __forceinline__ int kmap(int k) {
    return (k >> 3) * 8 + ((k & 3) << 1) + ((k >> 2) & 1);
}

// ---------------- kernel 1: TF32 mma.sync GEMM (131us champion, verbatim) ----------------
__global__ void __launch_bounds__(512, 1) main_kernel(
    const float* __restrict__ x, const float* __restrict__ mask,
    const float* __restrict__ proto,
    float* __restrict__ out_xcopy, float* __restrict__ out_mask)
{
    extern __shared__ float sm[];
    float* msk_s = sm;                 // [2][1024]
    float* buf_s = sm + 2 * MSK_F;     // [2][A_F + B_F]

    const int tid = threadIdx.x;
    const int wid = tid >> 5, lane = tid & 31;
    const int mt  = blockIdx.x >> 1;
    const int ks  = blockIdx.x & 1;
    const int b0  = mt * MTILE;
    const int c_beg = ks ? CSPL0 : 0;
    const int c_end = ks ? NCHT  : CSPL0;

    // mma roles: 16 warps = 4m x 4n
    const int tig = lane & 3, grp = lane >> 2;
    const int wm = wid & 3, wn = wid >> 2;
    const int boff = wm * 32, noff = wn * 16;

    float acc[2][2][4];
    #pragma unroll
    for (int i = 0; i < 2; i++)
        #pragma unroll
        for (int j = 0; j < 2; j++)
            #pragma unroll
            for (int q = 0; q < 4; q++) acc[i][j][q] = 0.f;
    float sqr[5] = {0.f, 0.f, 0.f, 0.f, 0.f};

    // staging registers
    float4 xv[5];
    float4 bv[3];
    float2 mnext;
    float  csqv;

    const int pb = tid & 63, tqb = tid >> 6;   // B csq role
    const int mrow = tid >> 2, mseg = tid & 3; // mask role

    auto ldg_x = [&](int c) {
        #pragma unroll
        for (int r = 0; r < 5; r++) {
            int idx = tid + 512 * r;
            int row = idx / 20, q = idx - row * 20;
            int goff = c * 80 + 4 * q;
            xv[r] = (goff < KD) ? __ldcs((const float4*)(x + (size_t)(b0 + row) * KD + goff))
                                : make_float4(0.f, 0.f, 0.f, 0.f);
        }
    };
    auto ldg_B = [&](int c) {
        #pragma unroll
        for (int r = 0; r < 3; r++) {
            int idx = tid + 512 * r;
            float4 v = make_float4(0.f, 0.f, 0.f, 0.f);
            if (idx < 1280) {
                int p = idx / 20, q = idx - p * 20;
                int goff = c * 80 + 4 * q;
                if (goff < KD) v = *(const float4*)(proto + (size_t)p * KD + goff);
            }
            bv[r] = v;
        }
        int tg = c * TC8 + tqb;
        csqv = 0.f;
        if (tg < TT) {
            const float2* cp = (const float2*)(proto + ((size_t)pb * TT + tg) * DD);
            #pragma unroll
            for (int q = 0; q < 5; q++) {
                float2 z = cp[q];
                csqv = fmaf(z.x, z.x, csqv);
                csqv = fmaf(z.y, z.y, csqv);
            }
        }
    };
    auto ldg_msk = [&](int c) {
        int t = c * TC8 + mseg * 2;
        float m0 = (t     < TT) ? __ldcs(mask + (size_t)(b0 + mrow) * TT + t)     : 0.f;
        float m1 = (t + 1 < TT) ? __ldcs(mask + (size_t)(b0 + mrow) * TT + t + 1) : 0.f;
        mnext = make_float2(m0, m1);
    };
    auto sts_msk = [&](int c) {
        float* ms = msk_s + (c & 1) * MSK_F;
        ms[mrow * 8 + mseg * 2]     = mnext.x;
        ms[mrow * 8 + mseg * 2 + 1] = mnext.y;
        int t = c * TC8 + mseg * 2;
        if (t     < TT) __stcs(out_mask + (size_t)(b0 + mrow) * TT + t,     mnext.x);
        if (t + 1 < TT) __stcs(out_mask + (size_t)(b0 + mrow) * TT + t + 1, mnext.y);
    };
    auto sts_AB = [&](int c) {
        float* a_s = buf_s + (c & 1) * BUF_F;
        float* b_s = a_s + A_F;
        const float* ms = msk_s + (c & 1) * MSK_F;
        // A: coalesced xcopy + masked tf32 scatter + fp32 sqx
        #pragma unroll
        for (int r = 0; r < 5; r++) {
            int idx = tid + 512 * r;
            int row = idx / 20, q = idx - row * 20;
            int goff = c * 80 + 4 * q;
            if (goff < KD)
                __stcs((float4*)(out_xcopy + (size_t)(b0 + row) * KD + goff), xv[r]);
            float e[4] = {xv[r].x, xv[r].y, xv[r].z, xv[r].w};
            #pragma unroll
            for (int u = 0; u < 4; u++) {
                int off = 4 * q + u;
                int t = off / 10, s = off - 10 * t;
                float m = ms[row * 8 + t];
                float vf = m * e[u];
                sqr[r] = fmaf(vf, e[u], sqr[r]);
                a_s[row * TS + kmap(t * SLOT + s)] = __uint_as_float(tf32r(vf));
            }
        }
        // A mask slots: 2 per thread (0/1 exact in tf32)
        #pragma unroll
        for (int j = 0; j < 2; j++) {
            int u2 = tid + 512 * j;
            int row = u2 >> 3, t = u2 & 7;
            a_s[row * TS + kmap(t * SLOT + 10)] = ms[row * 8 + t];
        }
        // B: -2c tf32 scatter
        #pragma unroll
        for (int r = 0; r < 3; r++) {
            int idx = tid + 512 * r;
            if (idx < 1280) {
                int p = idx / 20, q = idx - p * 20;
                float e[4] = {bv[r].x, bv[r].y, bv[r].z, bv[r].w};
                #pragma unroll
                for (int u = 0; u < 4; u++) {
                    int off = 4 * q + u;
                    int t = off / 10, s = off - 10 * t;
                    b_s[p * TS + kmap(t * SLOT + s)] = __uint_as_float(tf32r(-2.f * e[u]));
                }
            }
        }
        // B csq slot: 1 per thread
        b_s[pb * TS + kmap(tqb * SLOT + 10)] = __uint_as_float(tf32r(csqv));
    };
    auto mma_chunk = [&](int c) {
        const float* a_s = buf_s + (c & 1) * BUF_F;
        const float* b_s = a_s + A_F;
        #pragma unroll
        for (int kc = 0; kc < KCN; kc++) {
            uint32_t af[2][4], bf[2][2];
            #pragma unroll
            for (int i = 0; i < 2; i++) {
                int rb = boff + i * 16 + grp;
                float2 pa0 = *(const float2*)(a_s + rb * TS + kc * 8 + tig * 2);
                float2 pa1 = *(const float2*)(a_s + (rb + 8) * TS + kc * 8 + tig * 2);
                af[i][0] = __float_as_uint(pa0.x); af[i][2] = __float_as_uint(pa0.y);
                af[i][1] = __float_as_uint(pa1.x); af[i][3] = __float_as_uint(pa1.y);
            }
            #pragma unroll
            for (int j = 0; j < 2; j++) {
                int cp2 = noff + j * 8 + grp;
                float2 pbv = *(const float2*)(b_s + cp2 * TS + kc * 8 + tig * 2);
                bf[j][0] = __float_as_uint(pbv.x); bf[j][1] = __float_as_uint(pbv.y);
            }
            #pragma unroll
            for (int i = 0; i < 2; i++)
                #pragma unroll
                for (int j = 0; j < 2; j++)
                    asm volatile(
                        "mma.sync.aligned.m16n8k8.row.col.f32.tf32.tf32.f32 "
                        "{%0,%1,%2,%3}, {%4,%5,%6,%7}, {%8,%9}, {%0,%1,%2,%3};"
                        : "+f"(acc[i][j][0]), "+f"(acc[i][j][1]),
                          "+f"(acc[i][j][2]), "+f"(acc[i][j][3])
                        : "r"(af[i][0]), "r"(af[i][1]), "r"(af[i][2]), "r"(af[i][3]),
                          "r"(bf[j][0]), "r"(bf[j][1]));
        }
    };

    // prologue
    ldg_msk(c_beg); sts_msk(c_beg);
    if (c_beg + 1 < c_end) ldg_msk(c_beg + 1);
    ldg_x(c_beg); ldg_B(c_beg);
    __syncthreads();

    // 1-barrier pipeline: sts(c) | sts_msk(c+1) | sync | ldg(c+1) | mma(c)
    for (int c = c_beg; c < c_end; ++c) {
        sts_AB(c);
        if (c + 1 < c_end) sts_msk(c + 1);
        __syncthreads();
        if (c + 1 < c_end) { ldg_x(c + 1); ldg_B(c + 1); }
        if (c + 2 < c_end) ldg_msk(c + 2);
        mma_chunk(c);
    }

    // ---- sqx reduction (argmin invariant to per-b offset; order-free) ----
    __syncthreads();
    {
        float* red = msk_s;   // reuse
        if (tid < MTILE) red[tid] = 0.f;
        __syncthreads();
        #pragma unroll
        for (int r = 0; r < 5; r++) {
            int row = (tid + 512 * r) / 20;
            atomicAdd(&red[row], sqr[r]);
        }
        __syncthreads();
        if (tid < MTILE) g_sqx[ks][b0 + tid] = red[tid];
    }

    // ---- epilogue: accumulators -> g_partial ----
    #pragma unroll
    for (int i = 0; i < 2; i++) {
        int rb = b0 + boff + i * 16 + grp;
        #pragma unroll
        for (int j = 0; j < 2; j++) {
            int cc = noff + j * 8 + 2 * tig;
            *(float2*)&g_partial[ks][rb][cc]     = make_float2(acc[i][j][0], acc[i][j][1]);
            *(float2*)&g_partial[ks][rb + 8][cc] = make_float2(acc[i][j][2], acc[i][j][3]);
        }
    }
}

// ---------------- kernel 2: fused finalize — warp per b, deep-MLP gather ----------------
__global__ void __launch_bounds__(512) finalize_kernel(
    const float* __restrict__ x, const float* __restrict__ mask,
    const float* __restrict__ proto, const int* __restrict__ label,
    float* __restrict__ out_seq, float* __restrict__ out_dist,
    float* __restrict__ out_idx, float* __restrict__ out_label)
{
    const int tid = threadIdx.x, w = tid >> 5, lane = tid & 31;
    const int b = blockIdx.x * 16 + w;

    float sx = g_sqx[0][b] + g_sqx[1][b];
    float d0 = sx + g_partial[0][b][lane]      + g_partial[1][b][lane];
    float d1 = sx + g_partial[0][b][lane + 32] + g_partial[1][b][lane + 32];
    out_dist[(size_t)b * PP + lane]      = d0;
    out_dist[(size_t)b * PP + lane + 32] = d1;

    float bd; int bpick;
    if (d1 < d0) { bd = d1; bpick = lane + 32; } else { bd = d0; bpick = lane; }
    #pragma unroll
    for (int o = 16; o > 0; o >>= 1) {
        float od = __shfl_xor_sync(0xffffffffu, bd, o);
        int   op = __shfl_xor_sync(0xffffffffu, bpick, o);
        if (od < bd || (od == bd && op < bpick)) { bd = od; bpick = op; }
    }
    unsigned c0 = __ballot_sync(0xffffffffu, d0 < bd + MARGIN);
    unsigned c1 = __ballot_sync(0xffffffffu, d1 < bd + MARGIN);
    unsigned long long cm = ((unsigned long long)c1 << 32) | (unsigned long long)c0;
    int idx = bpick;
    if (__popcll(cm) > 1) {   // rare: exact fp32 rescore of near-ties
        float best = 3.4e38f; int bi = PP;
        while (cm) {
            int p = __ffsll((long long)cm) - 1;
            cm &= cm - 1;
            float r = 0.f;
            const float* xrow = x + (size_t)b * KD;
            const float* crow = proto + (size_t)p * KD;
            for (int t = lane; t < TT; t += 32) {
                float m = mask[(size_t)b * TT + t];
                if (m != 0.f) {
                    const float* xp = xrow + t * DD;
                    const float* cp = crow + t * DD;
                    float dot = 0.f, cps = 0.f;
                    #pragma unroll
                    for (int d = 0; d < DD; d++) {
                        float cv = cp[d];
                        dot = fmaf(xp[d], cv, dot);
                        cps = fmaf(cv, cv, cps);
                    }
                    r += cps - 2.f * dot;
                }
            }
            #pragma unroll
            for (int o = 16; o > 0; o >>= 1) r += __shfl_xor_sync(0xffffffffu, r, o);
            if (r < best) { best = r; bi = p; }   // ascending p: first-occurrence
        }
        idx = bi;
    }
    if (lane == 0) {
        out_idx[b]   = (float)idx;
        out_label[b] = (float)label[b];
    }

    // same warp gathers its row: out_seq[b] = proto[idx]; 8-deep load batches (MLP=8)
    const float4* src = (const float4*)(proto + (size_t)idx * KD);
    float4* dst = (float4*)(out_seq + (size_t)b * KD);
    int i = lane;
    #pragma unroll 2
    for (; i + 224 < KD / 4; i += 256) {
        float4 v0 = __ldg(src + i),       v1 = __ldg(src + i + 32);
        float4 v2 = __ldg(src + i + 64),  v3 = __ldg(src + i + 96);
        float4 v4 = __ldg(src + i + 128), v5 = __ldg(src + i + 160);
        float4 v6 = __ldg(src + i + 192), v7 = __ldg(src + i + 224);
        __stcs(dst + i,       v0); __stcs(dst + i + 32,  v1);
        __stcs(dst + i + 64,  v2); __stcs(dst + i + 96,  v3);
        __stcs(dst + i + 128, v4); __stcs(dst + i + 160, v5);
        __stcs(dst + i + 192, v6); __stcs(dst + i + 224, v7);
    }
    for (; i < KD / 4; i += 32) __stcs(dst + i, __ldg(src + i));
}

// ---------------- launch ----------------
extern "C" void kernel_launch(void* const* d_in, const int* in_sizes, int n_in,
                              void* d_out, int out_size) {
    const float* x     = (const float*)d_in[0];
    const int*   label = (const int*)d_in[1];
    const float* mask  = (const float*)d_in[2];
    const float* proto = (const float*)d_in[3];
    float* out = (float*)d_out;

    const size_t o_seq   = 0;
    const size_t o_xcopy = (size_t)BB * KD;
    const size_t o_dist  = o_xcopy * 2;
    const size_t o_idx   = o_dist + (size_t)BB * PP;
    const size_t o_label = o_idx + BB;
    const size_t o_mask  = o_label + BB;

    cudaFuncSetAttribute(main_kernel, cudaFuncAttributeMaxDynamicSharedMemorySize, SMEM_MAIN);

    main_kernel<<<NMT * KSPL, 512, SMEM_MAIN>>>(x, mask, proto,
                                                out + o_xcopy, out + o_mask);
    finalize_kernel<<<BB / 16, 512>>>(x, mask, proto, label,
                                      out + o_seq, out + o_dist,
                                      out + o_idx, out + o_label);
}